// round 15
// baseline (speedup 1.0000x reference)
#include <cuda_runtime.h>
#include <cuda_fp16.h>
#include <math.h>
#include <stdint.h>

// Problem constants
#define HID   1024
#define N1C   28
#define N2C   280
#define N3C   2800
#define BMAX  4096
// per-level N padded to 128-col tiles
#define N1P   128
#define N2P   384
#define N3P   2816
#define NT_COL 26             // 1 + 3 + 22 column tiles

#define NCH   16              // K chunks of 64 fp16 (128B) over K=1024

// ---------------------------------------------------------------------------
// Scratch (__device__ globals; allocation-free)
// ---------------------------------------------------------------------------
__device__ float g_z1[BMAX * N1C];
__device__ float g_z2[BMAX * N2C];
__device__ float g_anc[BMAX * N2C];          // fp32 z3 ancestors (cols 0..279)
__device__ __half g_z3h[BMAX * N3C];         // fp16 z3 (level 3)
__device__ float g_z3[BMAX * N3C];           // fallback logits3 if d_out too small
__device__ float g_blocksum[BMAX];
__device__ int   g_counter;

__device__ alignas(256) __half g_xc [BMAX * HID];
__device__ alignas(256) __half g_w1c[N1P  * HID];
__device__ alignas(256) __half g_w2c[N2P  * HID];
__device__ alignas(256) __half g_w3c[N3P  * HID];

// ---------------------------------------------------------------------------
// helpers
// ---------------------------------------------------------------------------
__device__ __forceinline__ uint32_t smem_u32(const void* p) {
    uint32_t a;
    asm("{ .reg .u64 t; cvta.to.shared.u64 t, %1; cvt.u32.u64 %0, t; }" : "=r"(a) : "l"(p));
    return a;
}
#define SWZ(off) ((off) ^ (((off) >> 3) & 0x70))

#define CP16(dst, src) \
    asm volatile("cp.async.cg.shared.global [%0], [%1], 16;" :: "r"(dst), "l"(src))
#define CP_COMMIT() asm volatile("cp.async.commit_group;" ::: "memory")
#define CP_WAIT(n)  asm volatile("cp.async.wait_group %0;" :: "n"(n) : "memory")

#define LDSM4(r0, r1, r2, r3, addr) \
    asm volatile("ldmatrix.sync.aligned.m8n8.x4.shared.b16 {%0,%1,%2,%3}, [%4];" \
                 : "=r"(r0), "=r"(r1), "=r"(r2), "=r"(r3) : "r"(addr))

#define MMA16816(d, a, b) \
    asm volatile("mma.sync.aligned.m16n8k16.row.col.f32.f16.f16.f32 " \
                 "{%0,%1,%2,%3}, {%4,%5,%6,%7}, {%8,%9}, {%0,%1,%2,%3};" \
                 : "+f"((d)[0]), "+f"((d)[1]), "+f"((d)[2]), "+f"((d)[3]) \
                 : "r"((a)[0]), "r"((a)[1]), "r"((a)[2]), "r"((a)[3]), \
                   "r"((b)[0]), "r"((b)[1]))

__device__ __forceinline__ float sigmoid_fast(float v) {
    return 1.f / (1.f + __expf(-v));
}

// ---------------------------------------------------------------------------
// Fused conversion: one block (256 thr) per row; 4 fp32 -> 4 fp16 per thread.
// ---------------------------------------------------------------------------
__global__ __launch_bounds__(256)
void convert_all_kernel(const float* __restrict__ x,
                        const float* __restrict__ W1,
                        const float* __restrict__ W2,
                        const float* __restrict__ W3,
                        __half* __restrict__ xc, __half* __restrict__ w1,
                        __half* __restrict__ w2, __half* __restrict__ w3,
                        int B)
{
    int blk = blockIdx.x;
    const float* src; __half* dst; int row, valid;
    if (blk < B)                         { src = x;  dst = xc; row = blk;                   valid = B;   }
    else if (blk < B + N1P)              { src = W1; dst = w1; row = blk - B;               valid = N1C; }
    else if (blk < B + N1P + N2P)        { src = W2; dst = w2; row = blk - B - N1P;         valid = N2C; }
    else                                 { src = W3; dst = w3; row = blk - B - N1P - N2P;   valid = N3C; }

    int k4 = threadIdx.x * 4;
    float4 v = make_float4(0.f, 0.f, 0.f, 0.f);
    if (row < valid) v = *(const float4*)(src + (size_t)row * HID + k4);
    __half2* d2 = (__half2*)(dst + (size_t)row * HID + k4);
    d2[0] = __half2{__float2half_rn(v.x), __float2half_rn(v.y)};
    d2[1] = __half2{__float2half_rn(v.z), __float2half_rn(v.w)};
}

// ---------------------------------------------------------------------------
// Fused fp16 mma.sync GEMM: Z = sigmoid(x @ W^T + b), K = 1024.
// CTA 128x128, 256 threads, 8 warps (2M x 4N, warp tile 64x32), 3 stages,
// 2 CTAs/SM. Level 1/2 -> fp32 z1/z2; level 3 -> fp16 z3h (+ fp32 ancestors).
// grid = (26, B/128).
// ---------------------------------------------------------------------------
#define STG   32768u           // A 16KB + B 16KB
#define SMEM_BYTES (1024u + 3u * STG)   // 99328

__global__ __launch_bounds__(256, 2)
void gemm_mma_kernel(const __half* __restrict__ xc,
                     const __half* __restrict__ w1c, const float* __restrict__ b1, float* __restrict__ z1,
                     const __half* __restrict__ w2c, const float* __restrict__ b2, float* __restrict__ z2,
                     const __half* __restrict__ w3c, const float* __restrict__ b3,
                     __half* __restrict__ z3h, float* __restrict__ anc)
{
    extern __shared__ char smem[];
    const uint32_t sb = (smem_u32(smem) + 1023u) & ~1023u;

    const int tid  = threadIdx.x;
    const int lane = tid & 31;
    const int w    = tid >> 5;
    const int brow = blockIdx.y;
    const int bcol = blockIdx.x;

    const __half* wc; const float* bias; int N, lcol;
    if (bcol == 0)      { wc = w1c; bias = b1; N = N1C; lcol = 0; }
    else if (bcol <= 3) { wc = w2c; bias = b2; N = N2C; lcol = bcol - 1; }
    else                { wc = w3c; bias = b3; N = N3C; lcol = bcol - 4; }

    const int m0 = brow * 128;
    const int n0 = lcol * 128;

    const char* Abase = (const char*)(xc + (size_t)m0 * HID);    // 2048 B/row
    const char* Bbase = (const char*)(wc + (size_t)n0 * HID);    // 2048 B/row

    auto issue_loads = [&](int c) {
        const uint32_t st = sb + (uint32_t)(c % 3) * STG;
        const int coff = c * 128;
#pragma unroll
        for (int it = 0; it < 4; it++) {
            int i = tid + it * 256;                  // 0..1023 (A: 128 rows)
            int row = i >> 3;
            int seg = (i & 7) * 16;
            CP16(st + SWZ((uint32_t)(row * 128 + seg)),
                 Abase + (size_t)row * 2048 + coff + seg);
        }
#pragma unroll
        for (int it = 0; it < 4; it++) {
            int i = tid + it * 256;                  // 0..1023 (B: 128 rows)
            int row = i >> 3;
            int seg = (i & 7) * 16;
            CP16(st + 16384u + SWZ((uint32_t)(row * 128 + seg)),
                 Bbase + (size_t)row * 2048 + coff + seg);
        }
        CP_COMMIT();
    };

    const int warpM = w & 1;                 // 2 warps along M (64 rows each)
    const int warpN = w >> 1;                // 4 warps along N (32 cols each)
    const int m0w = warpM * 64;
    const int n0w = warpN * 32;

    const uint32_t aRow = (uint32_t)((m0w + (lane & 15)) * 128 + (lane >> 4) * 16);
    const uint32_t bRow = (uint32_t)((n0w + (lane & 15)) * 128 + (lane >> 4) * 16);

    float acc[4][4][4];
#pragma unroll
    for (int i = 0; i < 4; i++)
#pragma unroll
        for (int j = 0; j < 4; j++)
#pragma unroll
            for (int r = 0; r < 4; r++) acc[i][j][r] = 0.f;

    issue_loads(0); issue_loads(1);

    for (int c = 0; c < NCH; c++) {
        if (c < NCH - 1) { CP_WAIT(1); } else { CP_WAIT(0); }
        __syncthreads();   // single barrier per chunk (multistage pattern)

        if (c + 2 < NCH) issue_loads(c + 2);

        const uint32_t Ast = sb + (uint32_t)(c % 3) * STG;
        const uint32_t Bst = Ast + 16384u;

#pragma unroll
        for (int ks = 0; ks < 4; ks++) {
            uint32_t a[4][4];
#pragma unroll
            for (int i = 0; i < 4; i++) {
                uint32_t ad = Ast + SWZ(aRow + (uint32_t)(i * 2048 + ks * 32));
                LDSM4(a[i][0], a[i][1], a[i][2], a[i][3], ad);
            }
            uint32_t bf[4][2];
#pragma unroll
            for (int jj = 0; jj < 2; jj++) {
                uint32_t bd = Bst + SWZ(bRow + (uint32_t)(jj * 2048 + ks * 32));
                uint32_t r0, r1, r2, r3;
                LDSM4(r0, r1, r2, r3, bd);
                bf[2*jj][0]   = r0; bf[2*jj][1]   = r2;
                bf[2*jj+1][0] = r1; bf[2*jj+1][1] = r3;
            }
#pragma unroll
            for (int i = 0; i < 4; i++)
#pragma unroll
                for (int j = 0; j < 4; j++)
                    MMA16816(acc[i][j], a[i], bf[j]);
        }
    }

    // ---- epilogue: bias + fast sigmoid ----
    if (bcol < 4) {
        float* Z = (bcol == 0) ? z1 : z2;
#pragma unroll
        for (int i = 0; i < 4; i++) {
            int row = m0 + m0w + i * 16 + (lane >> 2);
#pragma unroll
            for (int j = 0; j < 4; j++) {
                int col = n0 + n0w + j * 8 + (lane & 3) * 2;
                if (col >= N) continue;
                float bv0 = bias[col], bv1 = bias[col + 1];
                float2 v0, v1;
                v0.x = sigmoid_fast(acc[i][j][0] + bv0);
                v0.y = sigmoid_fast(acc[i][j][1] + bv1);
                v1.x = sigmoid_fast(acc[i][j][2] + bv0);
                v1.y = sigmoid_fast(acc[i][j][3] + bv1);
                *(float2*)(Z + (size_t)row * N + col)       = v0;
                *(float2*)(Z + (size_t)(row + 8) * N + col) = v1;
            }
        }
    } else {
        // level 3: fp16 store; cols < 280 additionally stored fp32 (ancestors)
#pragma unroll
        for (int i = 0; i < 4; i++) {
            int row = m0 + m0w + i * 16 + (lane >> 2);
#pragma unroll
            for (int j = 0; j < 4; j++) {
                int col = n0 + n0w + j * 8 + (lane & 3) * 2;
                if (col >= N3C) continue;
                float bv0 = bias[col], bv1 = bias[col + 1];
                float s00 = sigmoid_fast(acc[i][j][0] + bv0);
                float s01 = sigmoid_fast(acc[i][j][1] + bv1);
                float s10 = sigmoid_fast(acc[i][j][2] + bv0);
                float s11 = sigmoid_fast(acc[i][j][3] + bv1);
                *(__half2*)(z3h + (size_t)row * N3C + col) =
                    __half2{__float2half_rn(s00), __float2half_rn(s01)};
                *(__half2*)(z3h + (size_t)(row + 8) * N3C + col) =
                    __half2{__float2half_rn(s10), __float2half_rn(s11)};
                if (col < N2C) {   // col even, N2C even -> col+1 < N2C too
                    *(float2*)(anc + (size_t)row * N2C + col)       = float2{s00, s01};
                    *(float2*)(anc + (size_t)(row + 8) * N2C + col) = float2{s10, s11};
                }
            }
        }
    }
}

// ---------------------------------------------------------------------------
// Loss epilogue v5: fac from fp32 ancestors; z3 read as fp16; logits3 written
// once (fp32). Fused final mean via counter-gated last-block reduction.
// ---------------------------------------------------------------------------
__device__ __forceinline__ float blockSum512(float v, float* red) {
    int t = threadIdx.x;
#pragma unroll
    for (int off = 16; off; off >>= 1) v += __shfl_xor_sync(0xFFFFFFFFu, v, off);
    if ((t & 31) == 0) red[t >> 5] = v;
    __syncthreads();
    if (t == 0) {
        float s = 0.f;
#pragma unroll
        for (int k = 0; k < 16; k++) s += red[k];
        red[0] = s;
    }
    __syncthreads();
    float r = red[0];
    __syncthreads();
    return r;
}

__global__ __launch_bounds__(512)
void epilogue_kernel(const float* __restrict__ z1,
                     const float* __restrict__ z2,
                     const float* __restrict__ anc,
                     const __half* __restrict__ z3h,
                     const int*   __restrict__ labels,
                     float* __restrict__ outZ,
                     float* __restrict__ blocksum,
                     int* __restrict__ counter,
                     float* __restrict__ dst, int B)
{
    __shared__ float s1[N1C];
    __shared__ float s2[N2C];
    __shared__ float s3[N2C];
    __shared__ float fac[N2C + 8];
    __shared__ float red[16];
    __shared__ int isLast;

    const int b = blockIdx.x;
    const int t = threadIdx.x;
    const int lab  = labels[b];
    const int lab1 = lab / 100;
    const int lab2 = lab / 10;

    float* orow = outZ + (size_t)b * N3C;
    const __half* hrow = z3h + (size_t)b * N3C;

    if (t < N1C) s1[t] = z1[(size_t)b * N1C + t];
    if (t < N2C) s2[t] = z2[(size_t)b * N2C + t];
    if (t < 70) {                                  // 280 floats = 70 float4
        float4 v = *(const float4*)(anc + (size_t)b * N2C + t * 4);
        *(float4*)(s3 + t * 4) = v;
    }
    __syncthreads();

    float e1 = (t < N1C) ? __expf(s1[t]) : 0.f;
    float e2 = 0.f;
    if (t < N2C) {
        e2 = __expf(s2[t / 10] * s2[t]);
        fac[t] = s3[t / 10] * s3[t];
    }
    if (t >= N2C && t < N2C + 8) fac[t] = 0.f;
    __syncthreads();

    // level 3: logit = fac[k/10] * z3h[k]; fp16 read, fp32 write
    float e3 = 0.f;
#pragma unroll
    for (int it = 0; it < 2; it++) {
        int q = t + it * 512;
        if (q < 700) {
            int k = q * 4;
            int g0 = k / 10;
            int r  = k - g0 * 10;                   // r in {0,2,4,6,8}
            float fa = fac[g0], fb = fac[g0 + 1];
            uint2 raw = *(const uint2*)(hrow + k);  // 4 halves
            __half2 h0 = *(__half2*)&raw.x;
            __half2 h1 = *(__half2*)&raw.y;
            float2 za = __half22float2(h0);
            float2 zb = __half22float2(h1);
            float4 l4;
            l4.x = fa * za.x;
            l4.y = fa * za.y;
            l4.z = (r < 8 ? fa : fb) * zb.x;
            l4.w = (r < 7 ? fa : fb) * zb.y;
            *(float4*)(orow + k) = l4;
            e3 += __expf(l4.x) + __expf(l4.y) + __expf(l4.z) + __expf(l4.w);
        }
    }

    float sum1 = blockSum512(e1, red);
    float sum2 = blockSum512(e2, red);
    float sum3 = blockSum512(e3, red);   // syncthreads inside: orow writes visible

    if (t == 0) {
        float slab = orow[lab];
        float loss1 = logf(sum1) - s1[lab1];
        float loss2 = logf(sum2) - s2[lab2 / 10] * s2[lab2];
        float loss3 = logf(sum3) - slab;
        blocksum[b] = loss1 + loss2 + loss3;
        __threadfence();
        int old = atomicAdd(counter, 1);
        isLast = (old == gridDim.x - 1);
    }
    __syncthreads();

    if (isLast) {
        float s = 0.f;
        for (int i = t; i < B; i += 512) s += blocksum[i];
#pragma unroll
        for (int off = 16; off; off >>= 1) s += __shfl_xor_sync(0xFFFFFFFFu, s, off);
        if ((t & 31) == 0) red[t >> 5] = s;
        __syncthreads();
        if (t == 0) {
            float tot = 0.f;
#pragma unroll
            for (int k = 0; k < 16; k++) tot += red[k];
            if (dst) *dst = tot / (float)B;
            *counter = 0;
        }
    }
}

// ---------------------------------------------------------------------------
extern "C" void kernel_launch(void* const* d_in, const int* in_sizes, int n_in,
                              void* d_out, int out_size)
{
    const float* x      = (const float*)d_in[0];
    const int*   labels = (const int*)  d_in[1];
    const float* W1     = (const float*)d_in[2];
    const float* b1     = (const float*)d_in[3];
    const float* W2     = (const float*)d_in[4];
    const float* b2     = (const float*)d_in[5];
    const float* W3     = (const float*)d_in[6];
    const float* b3     = (const float*)d_in[7];

    int B = in_sizes[0] / HID;
    if (B > BMAX) B = BMAX;

    float* out = (float*)d_out;

    float *z1p, *z2p, *z3p, *ancp, *bsump;
    __half* z3hp;
    int* cntp;
    __half *xcp, *w1p, *w2p, *w3p;
    cudaGetSymbolAddress((void**)&z1p, g_z1);
    cudaGetSymbolAddress((void**)&z2p, g_z2);
    cudaGetSymbolAddress((void**)&z3p, g_z3);
    cudaGetSymbolAddress((void**)&ancp, g_anc);
    cudaGetSymbolAddress((void**)&z3hp, g_z3h);
    cudaGetSymbolAddress((void**)&bsump, g_blocksum);
    cudaGetSymbolAddress((void**)&cntp, g_counter);
    cudaGetSymbolAddress((void**)&xcp,  g_xc);
    cudaGetSymbolAddress((void**)&w1p,  g_w1c);
    cudaGetSymbolAddress((void**)&w2p,  g_w2c);
    cudaGetSymbolAddress((void**)&w3p,  g_w3c);

    convert_all_kernel<<<B + N1P + N2P + N3P, 256>>>(x, W1, W2, W3, xcp, w1p, w2p, w3p, B);

    const size_t LE = (size_t)B * N3C;
    float* zdst = ((size_t)out_size >= LE) ? out : z3p;

    float* lossdst = nullptr;
    if ((size_t)out_size > LE)                        lossdst = out + LE;
    else if ((size_t)out_size < LE && out_size >= 1)  lossdst = out;

    cudaFuncSetAttribute(gemm_mma_kernel, cudaFuncAttributeMaxDynamicSharedMemorySize, SMEM_BYTES);
    gemm_mma_kernel<<<dim3(NT_COL, B / 128), 256, SMEM_BYTES>>>(
        xcp,
        w1p, b1, z1p,
        w2p, b2, z2p,
        w3p, b3, z3hp, ancp);

    epilogue_kernel<<<B, 512>>>(z1p, z2p, ancp, z3hp, labels, zdst, bsump, cntp, lossdst, B);
}

// round 16
// speedup vs baseline: 1.0187x; 1.0187x over previous
#include <cuda_runtime.h>
#include <cuda_fp16.h>
#include <math.h>
#include <stdint.h>

// Problem constants
#define HID   1024
#define N1C   28
#define N2C   280
#define N3C   2800
#define BMAX  4096
// per-level N padded to 128-col tiles
#define N1P   128
#define N2P   384
#define N3P   2816
#define NT_COL 26             // 1 + 3 + 22 column tiles

#define NCH   16              // K chunks of 64 fp16 (128B) over K=1024

// ---------------------------------------------------------------------------
// Scratch (__device__ globals; allocation-free)
// ---------------------------------------------------------------------------
__device__ float g_z1[BMAX * N1C];
__device__ float g_z2[BMAX * N2C];
__device__ float g_z3[BMAX * N3C];
__device__ float g_blocksum[BMAX];
__device__ int   g_counter;

__device__ alignas(256) __half g_xc [BMAX * HID];
__device__ alignas(256) __half g_w1c[N1P  * HID];
__device__ alignas(256) __half g_w2c[N2P  * HID];
__device__ alignas(256) __half g_w3c[N3P  * HID];

// ---------------------------------------------------------------------------
// helpers
// ---------------------------------------------------------------------------
__device__ __forceinline__ uint32_t smem_u32(const void* p) {
    uint32_t a;
    asm("{ .reg .u64 t; cvta.to.shared.u64 t, %1; cvt.u32.u64 %0, t; }" : "=r"(a) : "l"(p));
    return a;
}
#define SWZ(off) ((off) ^ (((off) >> 3) & 0x70))

#define CP16(dst, src) \
    asm volatile("cp.async.cg.shared.global [%0], [%1], 16;" :: "r"(dst), "l"(src))
#define CP_COMMIT() asm volatile("cp.async.commit_group;" ::: "memory")
#define CP_WAIT(n)  asm volatile("cp.async.wait_group %0;" :: "n"(n) : "memory")

#define LDSM4(r0, r1, r2, r3, addr) \
    asm volatile("ldmatrix.sync.aligned.m8n8.x4.shared.b16 {%0,%1,%2,%3}, [%4];" \
                 : "=r"(r0), "=r"(r1), "=r"(r2), "=r"(r3) : "r"(addr))

#define MMA16816(d, a, b) \
    asm volatile("mma.sync.aligned.m16n8k16.row.col.f32.f16.f16.f32 " \
                 "{%0,%1,%2,%3}, {%4,%5,%6,%7}, {%8,%9}, {%0,%1,%2,%3};" \
                 : "+f"((d)[0]), "+f"((d)[1]), "+f"((d)[2]), "+f"((d)[3]) \
                 : "r"((a)[0]), "r"((a)[1]), "r"((a)[2]), "r"((a)[3]), \
                   "r"((b)[0]), "r"((b)[1]))

__device__ __forceinline__ float sigmoid_fast(float v) {
    return 1.f / (1.f + __expf(-v));
}

// ---------------------------------------------------------------------------
// Fused conversion: one block (256 thr) per row; 4 fp32 -> 4 fp16 per thread.
// ---------------------------------------------------------------------------
__global__ __launch_bounds__(256)
void convert_all_kernel(const float* __restrict__ x,
                        const float* __restrict__ W1,
                        const float* __restrict__ W2,
                        const float* __restrict__ W3,
                        __half* __restrict__ xc, __half* __restrict__ w1,
                        __half* __restrict__ w2, __half* __restrict__ w3,
                        int B)
{
    int blk = blockIdx.x;
    const float* src; __half* dst; int row, valid;
    if (blk < B)                         { src = x;  dst = xc; row = blk;                   valid = B;   }
    else if (blk < B + N1P)              { src = W1; dst = w1; row = blk - B;               valid = N1C; }
    else if (blk < B + N1P + N2P)        { src = W2; dst = w2; row = blk - B - N1P;         valid = N2C; }
    else                                 { src = W3; dst = w3; row = blk - B - N1P - N2P;   valid = N3C; }

    int k4 = threadIdx.x * 4;
    float4 v = make_float4(0.f, 0.f, 0.f, 0.f);
    if (row < valid) v = *(const float4*)(src + (size_t)row * HID + k4);
    __half2* d2 = (__half2*)(dst + (size_t)row * HID + k4);
    d2[0] = __half2{__float2half_rn(v.x), __float2half_rn(v.y)};
    d2[1] = __half2{__float2half_rn(v.z), __float2half_rn(v.w)};
}

// ---------------------------------------------------------------------------
// Fused fp16 mma.sync GEMM: Z = sigmoid(x @ W^T + b), K = 1024.
// CTA 128x128, 256 threads, 8 warps (2M x 4N, warp tile 64x32), 3 stages,
// 2 CTAs/SM. Single __syncthreads per K-chunk. grid = (26, B/128).
// ---------------------------------------------------------------------------
#define STG   32768u           // A 16KB + B 16KB
#define SMEM_BYTES (1024u + 3u * STG)   // 99328

__global__ __launch_bounds__(256, 2)
void gemm_mma_kernel(const __half* __restrict__ xc,
                     const __half* __restrict__ w1c, const float* __restrict__ b1, float* __restrict__ z1,
                     const __half* __restrict__ w2c, const float* __restrict__ b2, float* __restrict__ z2,
                     const __half* __restrict__ w3c, const float* __restrict__ b3, float* __restrict__ z3)
{
    extern __shared__ char smem[];
    const uint32_t sb = (smem_u32(smem) + 1023u) & ~1023u;

    const int tid  = threadIdx.x;
    const int lane = tid & 31;
    const int w    = tid >> 5;
    const int brow = blockIdx.y;
    const int bcol = blockIdx.x;

    const __half* wc; const float* bias; float* Z; int N, lcol;
    if (bcol == 0)      { wc = w1c; bias = b1; Z = z1; N = N1C; lcol = 0; }
    else if (bcol <= 3) { wc = w2c; bias = b2; Z = z2; N = N2C; lcol = bcol - 1; }
    else                { wc = w3c; bias = b3; Z = z3; N = N3C; lcol = bcol - 4; }

    const int m0 = brow * 128;
    const int n0 = lcol * 128;

    const char* Abase = (const char*)(xc + (size_t)m0 * HID);    // 2048 B/row
    const char* Bbase = (const char*)(wc + (size_t)n0 * HID);    // 2048 B/row

    auto issue_loads = [&](int c) {
        const uint32_t st = sb + (uint32_t)(c % 3) * STG;
        const int coff = c * 128;
#pragma unroll
        for (int it = 0; it < 4; it++) {
            int i = tid + it * 256;                  // 0..1023 (A: 128 rows)
            int row = i >> 3;
            int seg = (i & 7) * 16;
            CP16(st + SWZ((uint32_t)(row * 128 + seg)),
                 Abase + (size_t)row * 2048 + coff + seg);
        }
#pragma unroll
        for (int it = 0; it < 4; it++) {
            int i = tid + it * 256;                  // 0..1023 (B: 128 rows)
            int row = i >> 3;
            int seg = (i & 7) * 16;
            CP16(st + 16384u + SWZ((uint32_t)(row * 128 + seg)),
                 Bbase + (size_t)row * 2048 + coff + seg);
        }
        CP_COMMIT();
    };

    const int warpM = w & 1;                 // 2 warps along M (64 rows each)
    const int warpN = w >> 1;                // 4 warps along N (32 cols each)
    const int m0w = warpM * 64;
    const int n0w = warpN * 32;

    const uint32_t aRow = (uint32_t)((m0w + (lane & 15)) * 128 + (lane >> 4) * 16);
    const uint32_t bRow = (uint32_t)((n0w + (lane & 15)) * 128 + (lane >> 4) * 16);

    float acc[4][4][4];
#pragma unroll
    for (int i = 0; i < 4; i++)
#pragma unroll
        for (int j = 0; j < 4; j++)
#pragma unroll
            for (int r = 0; r < 4; r++) acc[i][j][r] = 0.f;

    issue_loads(0); issue_loads(1);

    for (int c = 0; c < NCH; c++) {
        if (c < NCH - 1) { CP_WAIT(1); } else { CP_WAIT(0); }
        __syncthreads();   // single barrier per chunk (multistage pattern)

        if (c + 2 < NCH) issue_loads(c + 2);

        const uint32_t Ast = sb + (uint32_t)(c % 3) * STG;
        const uint32_t Bst = Ast + 16384u;

#pragma unroll
        for (int ks = 0; ks < 4; ks++) {
            uint32_t a[4][4];
#pragma unroll
            for (int i = 0; i < 4; i++) {
                uint32_t ad = Ast + SWZ(aRow + (uint32_t)(i * 2048 + ks * 32));
                LDSM4(a[i][0], a[i][1], a[i][2], a[i][3], ad);
            }
            uint32_t bf[4][2];
#pragma unroll
            for (int jj = 0; jj < 2; jj++) {
                uint32_t bd = Bst + SWZ(bRow + (uint32_t)(jj * 2048 + ks * 32));
                uint32_t r0, r1, r2, r3;
                LDSM4(r0, r1, r2, r3, bd);
                bf[2*jj][0]   = r0; bf[2*jj][1]   = r2;
                bf[2*jj+1][0] = r1; bf[2*jj+1][1] = r3;
            }
#pragma unroll
            for (int i = 0; i < 4; i++)
#pragma unroll
                for (int j = 0; j < 4; j++)
                    MMA16816(acc[i][j], a[i], bf[j]);
        }
    }

    // ---- epilogue: bias + fast sigmoid, coalesced float2 stores ----
#pragma unroll
    for (int i = 0; i < 4; i++) {
        int row = m0 + m0w + i * 16 + (lane >> 2);
#pragma unroll
        for (int j = 0; j < 4; j++) {
            int col = n0 + n0w + j * 8 + (lane & 3) * 2;
            if (col >= N) continue;
            float bv0 = bias[col], bv1 = bias[col + 1];
            float2 v0, v1;
            v0.x = sigmoid_fast(acc[i][j][0] + bv0);
            v0.y = sigmoid_fast(acc[i][j][1] + bv1);
            v1.x = sigmoid_fast(acc[i][j][2] + bv0);
            v1.y = sigmoid_fast(acc[i][j][3] + bv1);
            *(float2*)(Z + (size_t)row * N + col)       = v0;
            *(float2*)(Z + (size_t)(row + 8) * N + col) = v1;
        }
    }
}

// ---------------------------------------------------------------------------
// Loss epilogue v6: divide-free level-3 transform via group factors, and the
// level-3 exp-sum via h2exp (ex2.approx.f16x2) -> 4x fewer MUFU ops.
// Fused final mean via counter-gated last-block reduction.
// ---------------------------------------------------------------------------
__device__ __forceinline__ float blockSum512(float v, float* red) {
    int t = threadIdx.x;
#pragma unroll
    for (int off = 16; off; off >>= 1) v += __shfl_xor_sync(0xFFFFFFFFu, v, off);
    if ((t & 31) == 0) red[t >> 5] = v;
    __syncthreads();
    if (t == 0) {
        float s = 0.f;
#pragma unroll
        for (int k = 0; k < 16; k++) s += red[k];
        red[0] = s;
    }
    __syncthreads();
    float r = red[0];
    __syncthreads();
    return r;
}

__global__ __launch_bounds__(512)
void epilogue_kernel(const float* __restrict__ z1,
                     const float* __restrict__ z2,
                     const int*   __restrict__ labels,
                     float* outZ,
                     float* __restrict__ blocksum,
                     int* __restrict__ counter,
                     float* __restrict__ dst, int B)
{
    __shared__ float s1[N1C];
    __shared__ float s2[N2C];
    __shared__ float s3[N2C];
    __shared__ float fac[N2C + 8];
    __shared__ float red[16];
    __shared__ int isLast;

    const int b = blockIdx.x;
    const int t = threadIdx.x;
    const int lab  = labels[b];
    const int lab1 = lab / 100;
    const int lab2 = lab / 10;

    float* orow = outZ + (size_t)b * N3C;

    if (t < N1C) s1[t] = z1[(size_t)b * N1C + t];
    if (t < N2C) s2[t] = z2[(size_t)b * N2C + t];
    if (t < 70) {                                  // 280 floats = 70 float4
        float4 v = *(const float4*)(orow + t * 4);
        *(float4*)(s3 + t * 4) = v;
    }
    __syncthreads();

    // level 1 + level 2 partials; level-3 group factors (one divide each)
    float e1 = (t < N1C) ? __expf(s1[t]) : 0.f;
    float e2 = 0.f;
    if (t < N2C) {
        e2 = __expf(s2[t / 10] * s2[t]);
        fac[t] = s3[t / 10] * s3[t];
    }
    if (t >= N2C && t < N2C + 8) fac[t] = 0.f;
    __syncthreads();

    // level 3: logit = fac[k/10] * z3[k]; float4 I/O; exp via f16x2 MUFU
    float e3 = 0.f;
#pragma unroll
    for (int it = 0; it < 2; it++) {
        int q = t + it * 512;
        if (q < 700) {
            int k = q * 4;
            int g0 = k / 10;                        // mul-shift, no IDIV
            int r  = k - g0 * 10;                   // r in {0,2,4,6,8}
            float fa = fac[g0], fb = fac[g0 + 1];
            float4 z4 = *(const float4*)(orow + k);
            float4 l4;
            l4.x = fa * z4.x;
            l4.y = fa * z4.y;
            l4.z = (r < 8 ? fa : fb) * z4.z;
            l4.w = (r < 7 ? fa : fb) * z4.w;
            *(float4*)(orow + k) = l4;
            // cheap exp: 2x h2exp (ex2.approx.f16x2) instead of 4x MUFU+FFMA.
            // Only the loss denominator uses this; logits3 output stays fp32.
            __half2 p0 = __floats2half2_rn(l4.x, l4.y);
            __half2 p1 = __floats2half2_rn(l4.z, l4.w);
            float2 f0 = __half22float2(h2exp(p0));
            float2 f1 = __half22float2(h2exp(p1));
            e3 += (f0.x + f0.y) + (f1.x + f1.y);
        }
    }

    float sum1 = blockSum512(e1, red);
    float sum2 = blockSum512(e2, red);
    float sum3 = blockSum512(e3, red);   // syncthreads inside: orow writes visible

    if (t == 0) {
        float slab = orow[lab];                     // transformed label logit
        float loss1 = logf(sum1) - s1[lab1];
        float loss2 = logf(sum2) - s2[lab2 / 10] * s2[lab2];
        float loss3 = logf(sum3) - slab;
        blocksum[b] = loss1 + loss2 + loss3;
        __threadfence();
        int old = atomicAdd(counter, 1);
        isLast = (old == gridDim.x - 1);
    }
    __syncthreads();

    if (isLast) {
        float s = 0.f;
        for (int i = t; i < B; i += 512) s += blocksum[i];
#pragma unroll
        for (int off = 16; off; off >>= 1) s += __shfl_xor_sync(0xFFFFFFFFu, s, off);
        if ((t & 31) == 0) red[t >> 5] = s;
        __syncthreads();
        if (t == 0) {
            float tot = 0.f;
#pragma unroll
            for (int k = 0; k < 16; k++) tot += red[k];
            if (dst) *dst = tot / (float)B;
            *counter = 0;                    // reset for next graph replay
        }
    }
}

// ---------------------------------------------------------------------------
extern "C" void kernel_launch(void* const* d_in, const int* in_sizes, int n_in,
                              void* d_out, int out_size)
{
    const float* x      = (const float*)d_in[0];
    const int*   labels = (const int*)  d_in[1];
    const float* W1     = (const float*)d_in[2];
    const float* b1     = (const float*)d_in[3];
    const float* W2     = (const float*)d_in[4];
    const float* b2     = (const float*)d_in[5];
    const float* W3     = (const float*)d_in[6];
    const float* b3     = (const float*)d_in[7];

    int B = in_sizes[0] / HID;
    if (B > BMAX) B = BMAX;

    float* out = (float*)d_out;

    float *z1p, *z2p, *z3p, *bsump;
    int* cntp;
    __half *xcp, *w1p, *w2p, *w3p;
    cudaGetSymbolAddress((void**)&z1p, g_z1);
    cudaGetSymbolAddress((void**)&z2p, g_z2);
    cudaGetSymbolAddress((void**)&z3p, g_z3);
    cudaGetSymbolAddress((void**)&bsump, g_blocksum);
    cudaGetSymbolAddress((void**)&cntp, g_counter);
    cudaGetSymbolAddress((void**)&xcp,  g_xc);
    cudaGetSymbolAddress((void**)&w1p,  g_w1c);
    cudaGetSymbolAddress((void**)&w2p,  g_w2c);
    cudaGetSymbolAddress((void**)&w3p,  g_w3c);

    convert_all_kernel<<<B + N1P + N2P + N3P, 256>>>(x, W1, W2, W3, xcp, w1p, w2p, w3p, B);

    const size_t LE = (size_t)B * N3C;
    float* zdst = ((size_t)out_size >= LE) ? out : z3p;

    float* lossdst = nullptr;
    if ((size_t)out_size > LE)                        lossdst = out + LE;
    else if ((size_t)out_size < LE && out_size >= 1)  lossdst = out;

    cudaFuncSetAttribute(gemm_mma_kernel, cudaFuncAttributeMaxDynamicSharedMemorySize, SMEM_BYTES);
    gemm_mma_kernel<<<dim3(NT_COL, B / 128), 256, SMEM_BYTES>>>(
        xcp,
        w1p, b1, z1p,
        w2p, b2, z2p,
        w3p, b3, zdst);

    epilogue_kernel<<<B, 512>>>(z1p, z2p, labels, zdst, bsump, cntp, lossdst, B);
}